// round 2
// baseline (speedup 1.0000x reference)
#include <cuda_runtime.h>
#include <cuda_bf16.h>

// ---------------- problem constants ----------------
constexpr int N_CHR = 50000, E_CHR = 500000;
constexpr int N_SLV = 30000, E_SLV = 300000;
constexpr int NTOT = N_CHR + N_SLV;      // 80000
constexpr int ETOT = E_CHR + E_SLV;      // 800000
constexpr int B    = 256;
constexpr int FEAT = 64;
constexpr int DIM  = 128;
constexpr int HALF = 64;
constexpr int ENS  = 3;

// ---------------- scratch (device globals; no allocations allowed) --------
__device__ float g_aggx[(size_t)NTOT * FEAT];          // 20.5 MB
__device__ float g_buf1[(size_t)NTOT * ENS * DIM];     // 123 MB
__device__ float g_buf2[(size_t)NTOT * ENS * DIM];     // 123 MB
__device__ float g_pool[(size_t)B * 2 * ENS * HALF];   // 256*384

// ---------------- utility: zero ----------------
__global__ void zero_kernel(float* __restrict__ p, int n4) {
    int i = blockIdx.x * blockDim.x + threadIdx.x;
    int stride = gridDim.x * blockDim.x;
    float4 z = make_float4(0.f, 0.f, 0.f, 0.f);
    for (; i < n4; i += stride) ((float4*)p)[i] = z;
}

// ---------------- vectorized atomic add -------------
__device__ __forceinline__ void red_add_v4(float* p, float4 v) {
    asm volatile("red.global.add.v4.f32 [%0], {%1,%2,%3,%4};"
                 :: "l"(p), "f"(v.x), "f"(v.y), "f"(v.z), "f"(v.w)
                 : "memory");
}

// ---------------- scatter: out[dst] += in[src], D multiple of 4 ----------
// One warp per edge; lanes stride over the D/4 float4 chunks of the row.
template<int D>
__global__ void scatter_kernel(const float* __restrict__ in, float* __restrict__ out,
                               const int* __restrict__ ei_chr, const int* __restrict__ ei_slv) {
    int lane = threadIdx.x & 31;
    int w  = (blockIdx.x * blockDim.x + threadIdx.x) >> 5;
    int nw = (gridDim.x * blockDim.x) >> 5;
    constexpr int C4 = D / 4;
    for (int e = w; e < ETOT; e += nw) {
        int src, dst;
        if (e < E_CHR) { src = ei_chr[e];                 dst = ei_chr[E_CHR + e]; }
        else { int e2 = e - E_CHR; src = N_CHR + ei_slv[e2]; dst = N_CHR + ei_slv[E_SLV + e2]; }
        const float4* s = (const float4*)(in + (size_t)src * D);
        float4* d = (float4*)(out + (size_t)dst * D);
        #pragma unroll
        for (int c = lane; c < C4; c += 32) {
            float4 v = s[c];
            red_add_v4((float*)(d + c), v);
        }
    }
}

// ---------------- scatter for D=64 (x features): 2 edges per warp ----------
__global__ void scatter64_kernel(const float* __restrict__ xchr, const float* __restrict__ xslv,
                                 float* __restrict__ out,
                                 const int* __restrict__ ei_chr, const int* __restrict__ ei_slv) {
    int lane = threadIdx.x & 31;
    int sub = lane >> 4;
    int l = lane & 15;
    int w  = (blockIdx.x * blockDim.x + threadIdx.x) >> 5;
    int nw = (gridDim.x * blockDim.x) >> 5;
    for (int ep = w; ep * 2 < ETOT; ep += nw) {
        int e = ep * 2 + sub;
        int src, dst; const float* x;
        if (e < E_CHR) { src = ei_chr[e]; dst = ei_chr[E_CHR + e]; x = xchr; }
        else { int e2 = e - E_CHR; src = ei_slv[e2]; dst = N_CHR + ei_slv[E_SLV + e2]; x = xslv; }
        float4 v = ((const float4*)(x + (size_t)src * FEAT))[l];
        red_add_v4((float*)(((float4*)(out + (size_t)dst * FEAT)) + l), v);
    }
}

// ---------------- GEMM: out[n, e*out_eoff + j] = (relu?)(in[n, e*in_eoff + :K] @ W[e]) --
// blockIdx.y = ensemble, blockIdx.z = branch (0=chr,1=slv); grid-strides over row tiles.
template<int K, int MOUT, bool RELU_IN, bool RELU_OUT>
__global__ __launch_bounds__(256)
void gemm_kernel(const float* __restrict__ in, float* __restrict__ out,
                 const float* __restrict__ Wc, const float* __restrict__ Ws,
                 int in_stride, int in_eoff, int out_stride, int out_eoff) {
    constexpr int GROUPS = 256 / MOUT;
    constexpr int R = 8;
    constexpr int TILE_R = GROUPS * R;
    constexpr int KPAD = K + 4;
    extern __shared__ float sm[];
    float* sW  = sm;                    // MOUT * KPAD  (transposed [j][k], padded)
    float* sIn = sm + MOUT * KPAD;      // TILE_R * K

    const int e = blockIdx.y;
    const int branch = blockIdx.z;
    const int tid = threadIdx.x;
    const int j = tid % MOUT;
    const int grp = tid / MOUT;

    const int base  = branch ? N_CHR : 0;
    const int nrows = branch ? N_SLV : N_CHR;
    const int ntiles = (nrows + TILE_R - 1) / TILE_R;
    const float* W = (branch ? Ws : Wc) + (size_t)e * K * MOUT;

    for (int idx = tid; idx < K * MOUT; idx += 256) {
        int k = idx / MOUT, jj = idx % MOUT;
        sW[jj * KPAD + k] = W[idx];
    }
    __syncthreads();

    for (int t = blockIdx.x; t < ntiles; t += gridDim.x) {
        int row0 = base + t * TILE_R;
        int rcnt = min(TILE_R, base + nrows - row0);
        constexpr int C4 = TILE_R * K / 4;
        for (int i = tid; i < C4; i += 256) {
            int r = i / (K / 4), kk = i % (K / 4);
            float4 v = make_float4(0.f, 0.f, 0.f, 0.f);
            if (r < rcnt) {
                v = *(const float4*)(in + (size_t)(row0 + r) * in_stride + (size_t)e * in_eoff + kk * 4);
                if (RELU_IN) {
                    v.x = fmaxf(v.x, 0.f); v.y = fmaxf(v.y, 0.f);
                    v.z = fmaxf(v.z, 0.f); v.w = fmaxf(v.w, 0.f);
                }
            }
            ((float4*)sIn)[i] = v;
        }
        __syncthreads();

        float acc[R];
        #pragma unroll
        for (int r = 0; r < R; r++) acc[r] = 0.f;
        const float4* w4 = (const float4*)(sW + j * KPAD);
        const float4* i4 = (const float4*)(sIn + grp * R * K);
        #pragma unroll 4
        for (int kk = 0; kk < K / 4; kk++) {
            float4 w = w4[kk];
            #pragma unroll
            for (int r = 0; r < R; r++) {
                float4 v = i4[r * (K / 4) + kk];
                acc[r] = fmaf(w.x, v.x, acc[r]);
                acc[r] = fmaf(w.y, v.y, acc[r]);
                acc[r] = fmaf(w.z, v.z, acc[r]);
                acc[r] = fmaf(w.w, v.w, acc[r]);
            }
        }
        #pragma unroll
        for (int r = 0; r < R; r++) {
            int rr = grp * R + r;
            if (rr < rcnt) {
                float v = acc[r];
                if (RELU_OUT) v = fmaxf(v, 0.f);
                out[(size_t)(row0 + rr) * out_stride + (size_t)e * out_eoff + j] = v;
            }
        }
        __syncthreads();
    }
}

// ---------------- pool: g_pool[batch[n]] += relu(agg2[n])  (stride 192) ----
__global__ void pool_kernel(const float* __restrict__ agg2,
                            const int* __restrict__ bchr, const int* __restrict__ bslv) {
    int i = blockIdx.x * blockDim.x + threadIdx.x;
    int stride = gridDim.x * blockDim.x;
    const int total = NTOT * 48;  // float4 chunks of the 192-wide rows
    for (; i < total; i += stride) {
        int n = i / 48, c = i % 48;
        float4 v = ((const float4*)(agg2 + (size_t)n * 192))[c];
        v.x = fmaxf(v.x, 0.f); v.y = fmaxf(v.y, 0.f);
        v.z = fmaxf(v.z, 0.f); v.w = fmaxf(v.w, 0.f);
        int b, colbase;
        if (n < N_CHR) { b = bchr[n]; colbase = 0; }
        else           { b = bslv[n - N_CHR]; colbase = 192; }
        red_add_v4(g_pool + (size_t)b * 384 + colbase + c * 4, v);
    }
}

// ---------------- head: projection heads + concat + fc1 + fc2 -------------
__global__ __launch_bounds__(128)
void head_kernel(const float* __restrict__ cfcW, const float* __restrict__ cfcb,
                 const float* __restrict__ sfcW, const float* __restrict__ sfcb,
                 const float* __restrict__ fc1W, const float* __restrict__ fc1b,
                 const float* __restrict__ fc2W, const float* __restrict__ fc2b,
                 float* __restrict__ out) {
    __shared__ float sPool[384];
    __shared__ float sHg[768];
    __shared__ float sRed[128];
    const int b = blockIdx.x;
    const int tid = threadIdx.x;

    for (int i = tid; i < 384; i += 128) sPool[i] = g_pool[(size_t)b * 384 + i];
    __syncthreads();

    #pragma unroll
    for (int p = 0; p < 6; p++) {
        const bool slv = (p >= 3);
        const int e = slv ? (p - 3) : p;
        const float* W = slv ? sfcW : cfcW;
        const float* bias = slv ? sfcb : cfcb;
        const float* rep = sPool + (slv ? 192 : 0) + e * HALF;
        float acc = bias[e * DIM + tid];
        #pragma unroll 8
        for (int k = 0; k < HALF; k++)
            acc = fmaf(rep[k], W[(size_t)e * HALF * DIM + k * DIM + tid], acc);
        sHg[p * DIM + tid] = fmaxf(acc, 0.f);
    }
    __syncthreads();

    float acc = fc1b[tid];
    #pragma unroll 8
    for (int h = 0; h < 768; h++)
        acc = fmaf(sHg[h], fc1W[(size_t)h * DIM + tid], acc);
    float o1 = fmaxf(acc, 0.f);

    sRed[tid] = o1 * fc2W[tid];
    __syncthreads();
    if (tid < 64) sRed[tid] += sRed[tid + 64];
    __syncthreads();
    if (tid < 32) {
        float x = sRed[tid] + sRed[tid + 32];
        #pragma unroll
        for (int o = 16; o; o >>= 1) x += __shfl_down_sync(0xffffffffu, x, o);
        if (tid == 0) out[b] = x + fc2b[0];
    }
}

// ---------------- launch ----------------
extern "C" void kernel_launch(void* const* d_in, const int* in_sizes, int n_in,
                              void* d_out, int out_size) {
    const float* chr_x  = (const float*)d_in[0];
    const float* slv_x  = (const float*)d_in[1];
    const int*   chr_ei = (const int*)d_in[2];
    const int*   slv_ei = (const int*)d_in[3];
    const int*   chr_b  = (const int*)d_in[4];
    const int*   slv_b  = (const int*)d_in[5];
    const float* chr_W0 = (const float*)d_in[6];
    const float* chr_W1 = (const float*)d_in[7];
    const float* chr_W2 = (const float*)d_in[8];
    const float* slv_W0 = (const float*)d_in[9];
    const float* slv_W1 = (const float*)d_in[10];
    const float* slv_W2 = (const float*)d_in[11];
    const float* cfcW   = (const float*)d_in[12];
    const float* cfcb   = (const float*)d_in[13];
    const float* sfcW   = (const float*)d_in[14];
    const float* sfcb   = (const float*)d_in[15];
    const float* fc1W   = (const float*)d_in[16];
    const float* fc1b   = (const float*)d_in[17];
    const float* fc2W   = (const float*)d_in[18];
    const float* fc2b   = (const float*)d_in[19];
    float* out = (float*)d_out;

    float *aggx, *buf1, *buf2, *pool;
    cudaGetSymbolAddress((void**)&aggx, g_aggx);
    cudaGetSymbolAddress((void**)&buf1, g_buf1);
    cudaGetSymbolAddress((void**)&buf2, g_buf2);
    cudaGetSymbolAddress((void**)&pool, g_pool);

    // dynamic smem sizes
    constexpr int SM0 = (128 * (64 + 4) + 16 * 64) * 4;    // 38912
    constexpr int SM1 = (128 * (128 + 4) + 16 * 128) * 4;  // 75776
    constexpr int SM2 = (64 * (128 + 4) + 32 * 128) * 4;   // 50176
    cudaFuncSetAttribute(gemm_kernel<64, 128, false, true>,  cudaFuncAttributeMaxDynamicSharedMemorySize, SM0);
    cudaFuncSetAttribute(gemm_kernel<128, 128, false, false>, cudaFuncAttributeMaxDynamicSharedMemorySize, SM1);
    cudaFuncSetAttribute(gemm_kernel<128, 64, true, false>,  cudaFuncAttributeMaxDynamicSharedMemorySize, SM2);

    const int ZGRID = 1184, SGRID = 1184;
    dim3 ggrid(148, ENS, 2);

    // 0) zero aggx + pool
    zero_kernel<<<ZGRID, 256>>>(aggx, NTOT * FEAT / 4);
    zero_kernel<<<4, 256>>>(pool, B * 384 / 4);
    // 1) aggx = A x  (shared across ensembles, dim 64)
    scatter64_kernel<<<SGRID, 256>>>(chr_x, slv_x, aggx, chr_ei, slv_ei);
    // 2) h0 = relu(aggx @ W0)  -> buf1 [N, 3*128]
    gemm_kernel<64, 128, false, true><<<ggrid, 256, SM0>>>(
        aggx, buf1, chr_W0, slv_W0, FEAT, 0, ENS * DIM, DIM);
    // 3) t1 = h0 @ W1 -> buf2
    gemm_kernel<128, 128, false, false><<<ggrid, 256, SM1>>>(
        buf1, buf2, chr_W1, slv_W1, ENS * DIM, DIM, ENS * DIM, DIM);
    // 4) agg1 = A t1 -> buf1
    zero_kernel<<<ZGRID, 256>>>(buf1, NTOT * ENS * DIM / 4);
    scatter_kernel<ENS * DIM><<<SGRID, 256>>>(buf2, buf1, chr_ei, slv_ei);
    // 5) t2 = relu(agg1) @ W2 -> buf2 [N, 3*64] (stride 192)
    gemm_kernel<128, 64, true, false><<<ggrid, 256, SM2>>>(
        buf1, buf2, chr_W2, slv_W2, ENS * DIM, DIM, ENS * HALF, HALF);
    // 6) agg2 = A t2 -> buf1 (192-wide region)
    zero_kernel<<<ZGRID, 256>>>(buf1, NTOT * ENS * HALF / 4);
    scatter_kernel<ENS * HALF><<<SGRID, 256>>>(buf2, buf1, chr_ei, slv_ei);
    // 7) pool[batch] += relu(agg2)
    pool_kernel<<<SGRID, 256>>>(buf1, chr_b, slv_b);
    // 8) head
    head_kernel<<<B, 128>>>(cfcW, cfcb, sfcW, sfcb, fc1W, fc1b, fc2W, fc2b, out);
}

// round 3
// speedup vs baseline: 1.5211x; 1.5211x over previous
#include <cuda_runtime.h>
#include <cuda_bf16.h>

// ---------------- problem constants ----------------
constexpr int N_CHR = 50000, E_CHR = 500000;
constexpr int N_SLV = 30000, E_SLV = 300000;
constexpr int NTOT = N_CHR + N_SLV;      // 80000
constexpr int ETOT = E_CHR + E_SLV;      // 800000
constexpr int B    = 256;
constexpr int FEAT = 64;
constexpr int DIM  = 128;
constexpr int HALF = 64;
constexpr int ENS  = 3;
constexpr int SCAN_BLK = 1024;
constexpr int NB_SCAN = (NTOT + SCAN_BLK - 1) / SCAN_BLK;  // 79

// ---------------- scratch (device globals; no allocations allowed) --------
__device__ float g_aggx[(size_t)NTOT * FEAT];
__device__ float g_buf1[(size_t)NTOT * ENS * DIM];
__device__ float g_buf2[(size_t)NTOT * ENS * DIM];
__device__ float g_pool[(size_t)B * 2 * ENS * HALF];
__device__ int   g_deg[NTOT];
__device__ int   g_incl[NTOT];
__device__ int   g_off[NTOT];
__device__ int   g_cursor[NTOT];
__device__ int   g_csr[ETOT];
__device__ int   g_bsumx[SCAN_BLK];  // exclusive-scanned block sums

// ---------------- utility ----------------
__global__ void zero_kernel(float* __restrict__ p, int n4) {
    int i = blockIdx.x * blockDim.x + threadIdx.x;
    int stride = gridDim.x * blockDim.x;
    float4 z = make_float4(0.f, 0.f, 0.f, 0.f);
    for (; i < n4; i += stride) ((float4*)p)[i] = z;
}

__device__ __forceinline__ void red_add_v4(float* p, float4 v) {
    asm volatile("red.global.add.v4.f32 [%0], {%1,%2,%3,%4};"
                 :: "l"(p), "f"(v.x), "f"(v.y), "f"(v.z), "f"(v.w)
                 : "memory");
}

__device__ __forceinline__ void edge_sd(int e, const int* __restrict__ ec,
                                        const int* __restrict__ es, int& src, int& dst) {
    if (e < E_CHR) { src = ec[e]; dst = ec[E_CHR + e]; }
    else { int e2 = e - E_CHR; src = N_CHR + es[e2]; dst = N_CHR + es[E_SLV + e2]; }
}

// ---------------- CSR build ----------------
__global__ void count_deg_kernel(const int* __restrict__ ec, const int* __restrict__ es) {
    int e = blockIdx.x * blockDim.x + threadIdx.x;
    if (e >= ETOT) return;
    int src, dst; edge_sd(e, ec, es, src, dst);
    atomicAdd(&g_deg[dst], 1);
}

__global__ void scan1_kernel(int* __restrict__ bsum_raw) {
    __shared__ int s[SCAN_BLK];
    int tid = threadIdx.x;
    int i = blockIdx.x * SCAN_BLK + tid;
    int v = (i < NTOT) ? g_deg[i] : 0;
    s[tid] = v;
    __syncthreads();
    #pragma unroll
    for (int off = 1; off < SCAN_BLK; off <<= 1) {
        int t = (tid >= off) ? s[tid - off] : 0;
        __syncthreads();
        s[tid] += t;
        __syncthreads();
    }
    if (i < NTOT) g_incl[i] = s[tid];
    if (tid == SCAN_BLK - 1) bsum_raw[blockIdx.x] = s[tid];
}

__global__ void scan2_kernel(const int* __restrict__ bsum_raw) {
    __shared__ int s[128];
    int tid = threadIdx.x;  // 128 threads, NB_SCAN=79 <=128
    int v = (tid < NB_SCAN) ? bsum_raw[tid] : 0;
    s[tid] = v;
    __syncthreads();
    #pragma unroll
    for (int off = 1; off < 128; off <<= 1) {
        int t = (tid >= off) ? s[tid - off] : 0;
        __syncthreads();
        s[tid] += t;
        __syncthreads();
    }
    g_bsumx[tid] = s[tid] - v;  // exclusive
}

__global__ void scan3_kernel() {
    int i = blockIdx.x * blockDim.x + threadIdx.x;
    if (i >= NTOT) return;
    int start = g_incl[i] - g_deg[i] + g_bsumx[i / SCAN_BLK];
    g_off[i] = start;
    g_cursor[i] = start;
}

__global__ void fill_csr_kernel(const int* __restrict__ ec, const int* __restrict__ es) {
    int e = blockIdx.x * blockDim.x + threadIdx.x;
    if (e >= ETOT) return;
    int src, dst; edge_sd(e, ec, es, src, dst);
    int pos = atomicAdd(&g_cursor[dst], 1);
    g_csr[pos] = src;
}

// ---------------- gather SpMM: out[n] = sum_{src in in-edges(n)} in[src], D floats --
__global__ __launch_bounds__(256)
void gather384_kernel(const float* __restrict__ in, float* __restrict__ out) {
    int lane = threadIdx.x & 31;
    int w = (blockIdx.x * blockDim.x + threadIdx.x) >> 5;
    if (w >= NTOT) return;
    int start = g_off[w], deg = g_deg[w];
    float4 a0 = make_float4(0,0,0,0), a1 = a0, a2 = a0;
    for (int kb = 0; kb < deg; kb += 32) {
        int idx = (kb + lane < deg) ? g_csr[start + kb + lane] : 0;
        int m = min(32, deg - kb);
        for (int k = 0; k < m; k++) {
            int s = __shfl_sync(0xffffffffu, idx, k);
            const float4* sr = (const float4*)(in + (size_t)s * 384);
            float4 v0 = sr[lane], v1 = sr[lane + 32], v2 = sr[lane + 64];
            a0.x += v0.x; a0.y += v0.y; a0.z += v0.z; a0.w += v0.w;
            a1.x += v1.x; a1.y += v1.y; a1.z += v1.z; a1.w += v1.w;
            a2.x += v2.x; a2.y += v2.y; a2.z += v2.z; a2.w += v2.w;
        }
    }
    float4* d = (float4*)(out + (size_t)w * 384);
    d[lane] = a0; d[lane + 32] = a1; d[lane + 64] = a2;
}

// layer-2 aggregation fused with relu + global_add_pool (rows are 192 wide)
__global__ __launch_bounds__(256)
void gather192_pool_kernel(const float* __restrict__ in,
                           const int* __restrict__ bchr, const int* __restrict__ bslv) {
    int lane = threadIdx.x & 31;
    int w = (blockIdx.x * blockDim.x + threadIdx.x) >> 5;
    if (w >= NTOT) return;
    int start = g_off[w], deg = g_deg[w];
    float4 a0 = make_float4(0,0,0,0), a1 = a0;
    for (int kb = 0; kb < deg; kb += 32) {
        int idx = (kb + lane < deg) ? g_csr[start + kb + lane] : 0;
        int m = min(32, deg - kb);
        for (int k = 0; k < m; k++) {
            int s = __shfl_sync(0xffffffffu, idx, k);
            const float4* sr = (const float4*)(in + (size_t)s * 192);
            float4 v0 = sr[lane];
            a0.x += v0.x; a0.y += v0.y; a0.z += v0.z; a0.w += v0.w;
            if (lane < 16) {
                float4 v1 = sr[lane + 32];
                a1.x += v1.x; a1.y += v1.y; a1.z += v1.z; a1.w += v1.w;
            }
        }
    }
    a0.x = fmaxf(a0.x, 0.f); a0.y = fmaxf(a0.y, 0.f); a0.z = fmaxf(a0.z, 0.f); a0.w = fmaxf(a0.w, 0.f);
    a1.x = fmaxf(a1.x, 0.f); a1.y = fmaxf(a1.y, 0.f); a1.z = fmaxf(a1.z, 0.f); a1.w = fmaxf(a1.w, 0.f);
    int b, colbase;
    if (w < N_CHR) { b = bchr[w]; colbase = 0; }
    else           { b = bslv[w - N_CHR]; colbase = 192; }
    float* prow = g_pool + (size_t)b * 384 + colbase;
    red_add_v4(prow + lane * 4, a0);
    if (lane < 16) red_add_v4(prow + 128 + lane * 4, a1);
}

// first aggregation over raw features (64 wide); 2 nodes per warp
__global__ __launch_bounds__(256)
void gather64_kernel(const float* __restrict__ xchr, const float* __restrict__ xslv,
                     float* __restrict__ out) {
    int lane = threadIdx.x & 31;
    int sub = lane >> 4;
    int l = lane & 15;
    int hw = ((blockIdx.x * blockDim.x + threadIdx.x) >> 5) * 2 + sub;
    if (hw >= NTOT) return;
    int start = g_off[hw], deg = g_deg[hw];
    float4 a0 = make_float4(0,0,0,0);
    for (int kb = 0; kb < deg; kb += 16) {
        int idx = (kb + l < deg) ? g_csr[start + kb + l] : 0;
        int m = min(16, deg - kb);
        for (int k = 0; k < m; k++) {
            int s = __shfl_sync(0xffffffffu, idx, k, 16);
            const float4* sr = (s < N_CHR) ? (const float4*)(xchr + (size_t)s * 64)
                                           : (const float4*)(xslv + (size_t)(s - N_CHR) * 64);
            float4 v = sr[l];
            a0.x += v.x; a0.y += v.y; a0.z += v.z; a0.w += v.w;
        }
    }
    ((float4*)(out + (size_t)hw * 64))[l] = a0;
}

// ---------------- register-tiled GEMM -------------------------------------
// out[n, e*out_eoff + j] = (relu?)( in[n, e*in_eoff + 0:K] @ W[e] )
// 256 threads; micro-tile 8 rows x MC cols per thread.
template<int K, int MOUT, int MC, bool RELU_IN, bool RELU_OUT>
__global__ __launch_bounds__(256, 1)
void gemm_kernel(const float* __restrict__ in, float* __restrict__ out,
                 const float* __restrict__ Wc, const float* __restrict__ Ws,
                 int in_stride, int in_eoff, int out_stride, int out_eoff) {
    constexpr int CG = MOUT / MC;       // col groups
    constexpr int RG = 256 / CG;        // row groups
    constexpr int TR = RG * 8;          // rows per tile
    constexpr int TRP = TR + 4;         // padded (keeps 16B alignment)
    extern __shared__ float sm[];
    float* sW   = sm;                   // [K][MOUT]
    float* sInT = sm + K * MOUT;        // [K][TRP] transposed input tile

    const int e = blockIdx.y;
    const int branch = blockIdx.z;
    const int tid = threadIdx.x;
    const int cgrp = tid % CG;
    const int rgrp = tid / CG;
    const int j0 = cgrp * MC;

    const int base  = branch ? N_CHR : 0;
    const int nrows = branch ? N_SLV : N_CHR;
    const int ntiles = (nrows + TR - 1) / TR;
    const float* W = (branch ? Ws : Wc) + (size_t)e * K * MOUT;

    for (int i = tid; i < K * MOUT / 4; i += 256)
        ((float4*)sW)[i] = ((const float4*)W)[i];
    __syncthreads();

    for (int t = blockIdx.x; t < ntiles; t += gridDim.x) {
        int row0 = base + t * TR;
        int rcnt = min(TR, base + nrows - row0);
        constexpr int C4 = TR * (K / 4);
        for (int i = tid; i < C4; i += 256) {
            int r = i / (K / 4), kc = i % (K / 4);
            float4 v = make_float4(0.f, 0.f, 0.f, 0.f);
            if (r < rcnt) {
                v = *(const float4*)(in + (size_t)(row0 + r) * in_stride + (size_t)e * in_eoff + kc * 4);
                if (RELU_IN) {
                    v.x = fmaxf(v.x, 0.f); v.y = fmaxf(v.y, 0.f);
                    v.z = fmaxf(v.z, 0.f); v.w = fmaxf(v.w, 0.f);
                }
            }
            int kk = kc * 4;
            sInT[(kk + 0) * TRP + r] = v.x;
            sInT[(kk + 1) * TRP + r] = v.y;
            sInT[(kk + 2) * TRP + r] = v.z;
            sInT[(kk + 3) * TRP + r] = v.w;
        }
        __syncthreads();

        float acc[8][MC];
        #pragma unroll
        for (int r = 0; r < 8; r++)
            #pragma unroll
            for (int c = 0; c < MC; c++) acc[r][c] = 0.f;

        #pragma unroll 4
        for (int k = 0; k < K; k++) {
            float4 A0 = *(const float4*)(sInT + k * TRP + rgrp * 8);
            float4 A1 = *(const float4*)(sInT + k * TRP + rgrp * 8 + 4);
            float a[8] = {A0.x, A0.y, A0.z, A0.w, A1.x, A1.y, A1.z, A1.w};
            float wv[MC];
            float4 W0 = *(const float4*)(sW + k * MOUT + j0);
            wv[0] = W0.x; wv[1] = W0.y; wv[2] = W0.z; wv[3] = W0.w;
            if (MC == 8) {
                float4 W1 = *(const float4*)(sW + k * MOUT + j0 + 4);
                wv[4] = W1.x; wv[5] = W1.y; wv[6] = W1.z; wv[7] = W1.w;
            }
            #pragma unroll
            for (int r = 0; r < 8; r++)
                #pragma unroll
                for (int c = 0; c < MC; c++)
                    acc[r][c] = fmaf(a[r], wv[c], acc[r][c]);
        }

        #pragma unroll
        for (int r = 0; r < 8; r++) {
            int rr = rgrp * 8 + r;
            if (rr < rcnt) {
                float* op = out + (size_t)(row0 + rr) * out_stride + (size_t)e * out_eoff + j0;
                #pragma unroll
                for (int c0 = 0; c0 < MC; c0 += 4) {
                    float4 v;
                    v.x = acc[r][c0 + 0]; v.y = acc[r][c0 + 1];
                    v.z = acc[r][c0 + 2]; v.w = acc[r][c0 + 3];
                    if (RELU_OUT) {
                        v.x = fmaxf(v.x, 0.f); v.y = fmaxf(v.y, 0.f);
                        v.z = fmaxf(v.z, 0.f); v.w = fmaxf(v.w, 0.f);
                    }
                    *(float4*)(op + c0) = v;
                }
            }
        }
        __syncthreads();
    }
}

// ---------------- head: projection heads + concat + fc1 + fc2 -------------
__global__ __launch_bounds__(128)
void head_kernel(const float* __restrict__ cfcW, const float* __restrict__ cfcb,
                 const float* __restrict__ sfcW, const float* __restrict__ sfcb,
                 const float* __restrict__ fc1W, const float* __restrict__ fc1b,
                 const float* __restrict__ fc2W, const float* __restrict__ fc2b,
                 float* __restrict__ out) {
    __shared__ float sPool[384];
    __shared__ float sHg[768];
    __shared__ float sRed[128];
    const int b = blockIdx.x;
    const int tid = threadIdx.x;

    for (int i = tid; i < 384; i += 128) sPool[i] = g_pool[(size_t)b * 384 + i];
    __syncthreads();

    #pragma unroll
    for (int p = 0; p < 6; p++) {
        const bool slv = (p >= 3);
        const int e = slv ? (p - 3) : p;
        const float* W = slv ? sfcW : cfcW;
        const float* bias = slv ? sfcb : cfcb;
        const float* rep = sPool + (slv ? 192 : 0) + e * HALF;
        float acc = bias[e * DIM + tid];
        #pragma unroll 8
        for (int k = 0; k < HALF; k++)
            acc = fmaf(rep[k], W[(size_t)e * HALF * DIM + k * DIM + tid], acc);
        sHg[p * DIM + tid] = fmaxf(acc, 0.f);
    }
    __syncthreads();

    float acc = fc1b[tid];
    #pragma unroll 8
    for (int h = 0; h < 768; h++)
        acc = fmaf(sHg[h], fc1W[(size_t)h * DIM + tid], acc);
    float o1 = fmaxf(acc, 0.f);

    sRed[tid] = o1 * fc2W[tid];
    __syncthreads();
    if (tid < 64) sRed[tid] += sRed[tid + 64];
    __syncthreads();
    if (tid < 32) {
        float x = sRed[tid] + sRed[tid + 32];
        #pragma unroll
        for (int o = 16; o; o >>= 1) x += __shfl_down_sync(0xffffffffu, x, o);
        if (tid == 0) out[b] = x + fc2b[0];
    }
}

// ---------------- launch ----------------
extern "C" void kernel_launch(void* const* d_in, const int* in_sizes, int n_in,
                              void* d_out, int out_size) {
    const float* chr_x  = (const float*)d_in[0];
    const float* slv_x  = (const float*)d_in[1];
    const int*   chr_ei = (const int*)d_in[2];
    const int*   slv_ei = (const int*)d_in[3];
    const int*   chr_b  = (const int*)d_in[4];
    const int*   slv_b  = (const int*)d_in[5];
    const float* chr_W0 = (const float*)d_in[6];
    const float* chr_W1 = (const float*)d_in[7];
    const float* chr_W2 = (const float*)d_in[8];
    const float* slv_W0 = (const float*)d_in[9];
    const float* slv_W1 = (const float*)d_in[10];
    const float* slv_W2 = (const float*)d_in[11];
    const float* cfcW   = (const float*)d_in[12];
    const float* cfcb   = (const float*)d_in[13];
    const float* sfcW   = (const float*)d_in[14];
    const float* sfcb   = (const float*)d_in[15];
    const float* fc1W   = (const float*)d_in[16];
    const float* fc1b   = (const float*)d_in[17];
    const float* fc2W   = (const float*)d_in[18];
    const float* fc2b   = (const float*)d_in[19];
    float* out = (float*)d_out;

    float *aggx, *buf1, *buf2, *pool;
    int *deg, *bsum_raw;
    cudaGetSymbolAddress((void**)&aggx, g_aggx);
    cudaGetSymbolAddress((void**)&buf1, g_buf1);
    cudaGetSymbolAddress((void**)&buf2, g_buf2);
    cudaGetSymbolAddress((void**)&pool, g_pool);
    cudaGetSymbolAddress((void**)&deg, g_deg);
    cudaGetSymbolAddress((void**)&bsum_raw, g_bsumx);  // reuse high half? no — separate raw below

    // use g_incl's tail? keep it simple: raw block sums go in a dedicated spot:
    static_assert(NB_SCAN <= 128, "");

    // smem sizes
    constexpr int SM0 = (64  * 128 + 64  * 132) * 4;   // 66560
    constexpr int SM1 = (128 * 128 + 128 * 132) * 4;   // 133120
    constexpr int SM2 = (128 * 64  + 128 * 132) * 4;   // 100352
    cudaFuncSetAttribute((const void*)gemm_kernel<64, 128, 8, false, true>,
                         cudaFuncAttributeMaxDynamicSharedMemorySize, SM0);
    cudaFuncSetAttribute((const void*)gemm_kernel<128, 128, 8, false, false>,
                         cudaFuncAttributeMaxDynamicSharedMemorySize, SM1);
    cudaFuncSetAttribute((const void*)gemm_kernel<128, 64, 4, true, false>,
                         cudaFuncAttributeMaxDynamicSharedMemorySize, SM2);

    dim3 ggrid(148, ENS, 2);

    // ---- CSR build (per-launch; deterministic work) ----
    zero_kernel<<<40, 256>>>((float*)deg, NTOT / 4);
    zero_kernel<<<4, 256>>>(pool, B * 384 / 4);
    count_deg_kernel<<<(ETOT + 255) / 256, 256>>>(chr_ei, slv_ei);
    {
        // raw block sums: stash in g_cursor[0..NB_SCAN) temporarily? No —
        // g_cursor written by scan3 later. Use a small dedicated buffer: reuse
        // tail of g_csr (written only by fill, after scan completes).
        int* raw;
        cudaGetSymbolAddress((void**)&raw, g_csr);
        raw += ETOT - 128;  // last 128 ints of g_csr as scratch (fill overwrites later)
        scan1_kernel<<<NB_SCAN, SCAN_BLK>>>(raw);
        scan2_kernel<<<1, 128>>>(raw);
    }
    scan3_kernel<<<(NTOT + 255) / 256, 256>>>();
    fill_csr_kernel<<<(ETOT + 255) / 256, 256>>>(chr_ei, slv_ei);

    // ---- forward pass ----
    // 1) aggx = A x   (shared across ensembles, 64 wide)
    gather64_kernel<<<(NTOT / 2 + 7) / 8, 256>>>(chr_x, slv_x, aggx);
    // 2) h0 = relu(aggx @ W0) -> buf1 [N, 3*128]
    gemm_kernel<64, 128, 8, false, true><<<ggrid, 256, SM0>>>(
        aggx, buf1, chr_W0, slv_W0, FEAT, 0, ENS * DIM, DIM);
    // 3) t1 = h0 @ W1 -> buf2
    gemm_kernel<128, 128, 8, false, false><<<ggrid, 256, SM1>>>(
        buf1, buf2, chr_W1, slv_W1, ENS * DIM, DIM, ENS * DIM, DIM);
    // 4) agg1 = A t1 -> buf1
    gather384_kernel<<<NTOT / 8, 256>>>(buf2, buf1);
    // 5) t2 = relu(agg1) @ W2 -> buf2 [N, 3*64]
    gemm_kernel<128, 64, 4, true, false><<<ggrid, 256, SM2>>>(
        buf1, buf2, chr_W2, slv_W2, ENS * DIM, DIM, ENS * HALF, HALF);
    // 6) pool[batch] += relu(A t2)   (fused aggregation + relu + pool)
    gather192_pool_kernel<<<NTOT / 8, 256>>>(buf2, chr_b, slv_b);
    // 7) head
    head_kernel<<<B, 128>>>(cfcW, cfcb, sfcW, sfcb, fc1W, fc1b, fc2W, fc2b, out);
}